// round 9
// baseline (speedup 1.0000x reference)
#include <cuda_runtime.h>
#include <cuda.h>
#include <cuda_bf16.h>
#include <cuda_fp16.h>
#include <math.h>
#include <stdint.h>

// ---------------------------------------------------------------------------
// CircleLoss, ticket-cascade edition (3 launches):
//   1) sort_labels : label dtype detect + deterministic stable counting sort
//   2) to_fp16p    : gather-permuted E -> fp16 scratch
//   3) gemm_fused  : triangular grid (528 CTAs), fp16 mma.sync GEMM +
//                    per-tile row/col partial reduction (L-form, 8 floats) +
//                    deterministic ticket cascade: the CTA completing a
//                    row-block's 32 partials merges it in fixed order; the
//                    last block-finisher folds 32 block sums -> out[0..3].
// ---------------------------------------------------------------------------

#define MAXB 4096
#define MAXD 512
#define NBLK 32

__device__ __half g_eth[MAXB * MAXD];          // 4 MB permuted fp16 embeddings
__device__ float  g_part[MAXB * 32 * 8];       // 4.2 MB partial states (L-form)
__device__ float4 g_bsum[NBLK];                // per-row-block sums
__device__ int    g_perm[MAXB];
__device__ int    g_cs[MAXB];
__device__ int    g_ce[MAXB];
__device__ int    g_cnt128[NBLK];              // per-row-block completion count
__device__ int    g_cntFin = 0;                // block-finisher ticket

#define SCALE_C   32.0f
#define MARGIN_P  0.75f
#define MARGIN_N  0.25f
#define OPT_P     1.25f
#define OPT_N     (-0.25f)
#define THETA_C   0.25f
#define NEG_INF   (-INFINITY)

// ------------------------------ helpers ------------------------------------
__device__ __forceinline__ uint32_t smem_u32(const void* p) {
    uint32_t a;
    asm("{ .reg .u64 t; cvta.to.shared.u64 t, %1; cvt.u32.u64 %0, t; }"
        : "=r"(a) : "l"(p));
    return a;
}
__device__ __forceinline__ void cp_async16(uint32_t dst, const void* src) {
    asm volatile("cp.async.cg.shared.global [%0], [%1], 16;" :: "r"(dst), "l"(src));
}
__device__ __forceinline__ void ldm_x4(uint32_t* r, uint32_t addr) {
    asm volatile("ldmatrix.sync.aligned.m8n8.x4.shared.b16 {%0,%1,%2,%3}, [%4];"
        : "=r"(r[0]), "=r"(r[1]), "=r"(r[2]), "=r"(r[3]) : "r"(addr));
}
__device__ __forceinline__ void mma_f16_frag(float* d, const uint32_t* a, const uint32_t* b) {
    asm volatile(
        "mma.sync.aligned.m16n8k16.row.col.f32.f16.f16.f32 "
        "{%0,%1,%2,%3}, {%4,%5,%6,%7}, {%8,%9}, {%0,%1,%2,%3};"
        : "+f"(d[0]), "+f"(d[1]), "+f"(d[2]), "+f"(d[3])
        : "r"(a[0]), "r"(a[1]), "r"(a[2]), "r"(a[3]), "r"(b[0]), "r"(b[1]));
}
__device__ __forceinline__ void lse_add(float& m, float& s, float v) {
    if (v > m) { s = s * expf(m - v) + 1.0f; m = v; }
    else       { s += expf(v - m); }
}
__device__ __forceinline__ void lse_merge(float& m1, float& s1, float m2, float s2) {
    if (m2 == NEG_INF) return;
    if (m2 > m1) { s1 = s1 * expf(m1 - m2) + s2; m1 = m2; }
    else         { s1 += s2 * expf(m2 - m1); }
}
__device__ __forceinline__ float lse_close(float m, float s) {
    return (m == NEG_INF) ? NEG_INF : m + logf(s);
}

struct St {
    float pmin, nmax, m1, s1, m2, s2, m3, s3, m4, s4;
    __device__ __forceinline__ void init() {
        pmin = INFINITY; nmax = NEG_INF;
        m1 = m2 = m3 = m4 = NEG_INF; s1 = s2 = s3 = s4 = 0.f;
    }
    __device__ __forceinline__ void upd(float s, int j, int cs, int ce) {
        if (j >= cs && j < ce) {                       // positive (incl. self)
            pmin = fminf(pmin, s);
            if (s < MARGIN_P) {
                float ip = -SCALE_C * fmaxf(OPT_P - s, 0.0f) * (s - MARGIN_P);
                lse_add(m2, s2, ip);
                if (s + THETA_C < MARGIN_P) lse_add(m1, s1, ip);
            }
        } else {
            nmax = fmaxf(nmax, s);
            if (s > MARGIN_N) {
                float in_ = SCALE_C * fmaxf(s - OPT_N, 0.0f) * (s - MARGIN_N);
                lse_add(m4, s4, in_);
                if (s - THETA_C > MARGIN_N) lse_add(m3, s3, in_);
            }
        }
    }
    // L-form store: 8 floats = pmin, nmax, L1..L4, pad, pad
    __device__ __forceinline__ void storeL(float* p) const {
        ((float4*)p)[0] = make_float4(pmin, nmax, lse_close(m1, s1), lse_close(m2, s2));
        ((float4*)p)[1] = make_float4(lse_close(m3, s3), lse_close(m4, s4), 0.f, 0.f);
    }
};

// ------------------------- deterministic sort -------------------------------
#define NC 128
#define SORT_SMEM (MAXB * 4 + 256 * NC * 2 + (NC + 1) * 4 + 64)

__global__ void sort_labels(const void* __restrict__ lab, int B) {
    extern __shared__ char sms[];
    int* slab = (int*)sms;
    unsigned short* hist = (unsigned short*)(sms + MAXB * 4);
    int* cstart = (int*)(sms + MAXB * 4 + 256 * NC * 2);

    const int t = threadIdx.x;
    const int chk = B / 256;

    __shared__ int is64;
    if (t == 0) {
        const long long* p = (const long long*)lab;
        int ok = 1;
        int n = B < 64 ? B : 64;
        for (int i = 0; i < n; i++) {
            long long v = p[i];
            if (v < 0 || v >= (long long)B) { ok = 0; break; }
        }
        is64 = ok;
    }
    __syncthreads();
    if (is64) {
        const long long* p = (const long long*)lab;
        for (int i = t; i < B; i += 256) slab[i] = (int)p[i];
    } else {
        const int* p = (const int*)lab;
        for (int i = t; i < B; i += 256) slab[i] = p[i];
    }
    for (int i = t; i < 256 * NC; i += 256) hist[i] = 0;
    __syncthreads();

    for (int k = 0; k < chk; k++) hist[t * NC + slab[t * chk + k]]++;
    __syncthreads();

    if (t < NC) {
        int sum = 0;
        for (int ch = 0; ch < 256; ch++) sum += hist[ch * NC + t];
        cstart[t + 1] = sum;
    }
    __syncthreads();
    if (t == 0) {
        cstart[0] = 0;
        for (int c = 1; c <= NC; c++) cstart[c] += cstart[c - 1];
    }
    __syncthreads();
    if (t < NC) {
        int run = cstart[t];
        for (int ch = 0; ch < 256; ch++) {
            int v = hist[ch * NC + t];
            hist[ch * NC + t] = (unsigned short)run;
            run += v;
        }
    }
    __syncthreads();

    for (int k = 0; k < chk; k++) {
        int i = t * chk + k;
        int c = slab[i];
        int p = hist[t * NC + c]++;
        g_perm[p] = i;
    }
    __syncthreads();

    for (int r = t; r < B; r += 256) {
        int c = slab[g_perm[r]];
        g_cs[r] = cstart[c];
        g_ce[r] = cstart[c + 1];
    }
}

// ------------------- permuted fp16 conversion (gather) ----------------------
__global__ __launch_bounds__(128) void to_fp16p(const float* __restrict__ e, int D) {
    const int r = blockIdx.x;
    const int pr = g_perm[r];
    const float4* src = (const float4*)(e + (size_t)pr * D);
    __half2* dst = (__half2*)(g_eth + (size_t)r * D);
    for (int d = threadIdx.x; d < D / 4; d += 128) {
        float4 v = src[d];
        dst[2 * d + 0] = __floats2half2_rn(v.x, v.y);
        dst[2 * d + 1] = __floats2half2_rn(v.z, v.w);
    }
}

// ------------------------ fused GEMM + full reduction -----------------------
#define BK 64
#define PH 72                                  // smem pitch in halves (144 B)
#define STAGE_BYTES (2 * 128 * PH * 2)         // A + B per stage = 36864
#define NSTG 3
#define TS 132                                 // reduction tile pitch (floats)
#define SMEM_GEMM (NSTG * STAGE_BYTES)         // 110592 >= 128*TS*4 = 67584

// Merge one row-block (128 rows x 32 slots) and post its sum. Deterministic:
// fixed slot order, fixed tree. Executed by the CTA whose ticket completed it.
__device__ void finish_block(int i, float* sm, float* out, int B) {
    const int tid = threadIdx.x;
    float4 res = make_float4(0.f, 0.f, 0.f, 0.f);
    if (tid < 128) {
        const int gr = i * 128 + tid;
        St st; st.init();
        const float4* p = (const float4*)&g_part[(size_t)gr * 32 * 8];
#pragma unroll 4
        for (int k = 0; k < 32; k++) {
            float4 a = __ldcg(p + 2 * k);
            float4 b = __ldcg(p + 2 * k + 1);
            st.pmin = fminf(st.pmin, a.x);
            st.nmax = fmaxf(st.nmax, a.y);
            lse_merge(st.m1, st.s1, a.z, 1.f);
            lse_merge(st.m2, st.s2, a.w, 1.f);
            lse_merge(st.m3, st.s3, b.x, 1.f);
            lse_merge(st.m4, st.s4, b.y, 1.f);
        }
        float se_pos;
        if (st.m1 > NEG_INF)      se_pos = st.m1 + logf(st.s1);
        else if (st.m2 > NEG_INF) se_pos = st.m2 + logf(st.s2);
        else se_pos = -SCALE_C * fmaxf(OPT_P - st.pmin, 0.0f) * (st.pmin - MARGIN_P);
        float se_neg;
        if (st.m3 > NEG_INF)      se_neg = st.m3 + logf(st.s3);
        else if (st.m4 > NEG_INF) se_neg = st.m4 + logf(st.s4);
        else if (st.nmax > NEG_INF)
            se_neg = SCALE_C * fmaxf(st.nmax - OPT_N, 0.0f) * (st.nmax - MARGIN_N);
        else se_neg = 0.0f;

        float z = se_pos + se_neg;
        float pl = (z > 0.0f) ? (z + log1pf(expf(-z))) : log1pf(expf(z));
        float lowf  = (st.pmin > st.nmax) ? 1.0f : 0.0f;
        float medf  = (lowf != 0.0f && st.pmin > MARGIN_P) ? 1.0f : 0.0f;
        float highf = (medf != 0.0f && st.nmax < MARGIN_N) ? 1.0f : 0.0f;
        res = make_float4(pl, lowf, medf, highf);
    }
    // block tree-sum of 256 float4 (upper half zeros) in dynamic smem
    float4* shr = (float4*)sm;
    shr[tid] = res;
    __syncthreads();
    for (int off = 128; off > 0; off >>= 1) {
        if (tid < off) {
            float4 x = shr[tid], y = shr[tid + off];
            shr[tid] = make_float4(x.x + y.x, x.y + y.y, x.z + y.z, x.w + y.w);
        }
        __syncthreads();
    }
    __shared__ int lastFin;
    if (tid == 0) {
        g_bsum[i] = shr[0];
        g_cnt128[i] = 0;                        // reset for next replay
        __threadfence();
        lastFin = atomicAdd(&g_cntFin, 1);
    }
    __syncthreads();
    if (lastFin == NBLK - 1) {                  // final fold: 32 block sums
        if (tid == 0) {
            float4 a = make_float4(0.f, 0.f, 0.f, 0.f);
#pragma unroll
            for (int k = 0; k < NBLK; k++) {
                float4 b = __ldcg(&g_bsum[k]);
                a.x += b.x; a.y += b.y; a.z += b.z; a.w += b.w;
            }
            float inv = 1.0f / (float)B;
            out[0] = a.x * inv;
            out[1] = a.y * inv;
            out[2] = a.z * inv;
            out[3] = a.w * inv;
            g_cntFin = 0;                       // reset for next replay
        }
    }
}

__global__ __launch_bounds__(256, 2) void gemm_fused(float* __restrict__ out, int B, int D) {
    // linear -> triangular (by <= bx)
    const int t = blockIdx.x;
    int bx = (int)((sqrtf(8.0f * t + 1.0f) - 1.0f) * 0.5f);
    while ((bx + 1) * (bx + 2) / 2 <= t) bx++;
    while (bx * (bx + 1) / 2 > t) bx--;
    const int by = t - bx * (bx + 1) / 2;

    extern __shared__ float sm[];
    const uint32_t smb = smem_u32(sm);
    const int tid  = threadIdx.x;
    const int warp = tid >> 5, lane = tid & 31;
    const int wm = warp & 1, wn = warp >> 1;       // 2 x 4 warp grid
    const int fr = lane >> 2, fq = lane & 3;

    const __half* gA = g_eth + (size_t)(by * 128) * D;
    const __half* gB = g_eth + (size_t)(bx * 128) * D;

    float acc[4][4][4];
#pragma unroll
    for (int mt = 0; mt < 4; mt++)
#pragma unroll
        for (int nt = 0; nt < 4; nt++)
#pragma unroll
            for (int e = 0; e < 4; e++) acc[mt][nt][e] = 0.0f;

    const int nK = D / BK;                          // 8

#define LOAD_STAGE(s, k0)                                                      \
    do {                                                                       \
        uint32_t ab = smb + (uint32_t)(s) * STAGE_BYTES;                       \
        uint32_t bb = ab + 128 * PH * 2;                                       \
        _Pragma("unroll")                                                      \
        for (int i = 0; i < 4; i++) {                                          \
            int c = tid + 256 * i;                                             \
            int r = c >> 3;                                                    \
            int kc = (c & 7) << 3;                                             \
            cp_async16(ab + (uint32_t)(r * PH + kc) * 2,                       \
                       gA + (size_t)r * D + (k0) + kc);                        \
            cp_async16(bb + (uint32_t)(r * PH + kc) * 2,                       \
                       gB + (size_t)r * D + (k0) + kc);                        \
        }                                                                      \
        asm volatile("cp.async.commit_group;" ::: "memory");                   \
    } while (0)

    LOAD_STAGE(0, 0);
    LOAD_STAGE(1, BK);

    const int a_lr = lane & 15, a_kh = lane >> 4;     // A: row 0-15, k-half
    const int b_gr = lane >> 3, b_rw = lane & 7;      // B: group 0-3, row 0-7

    for (int kt = 0; kt < nK; kt++) {
        if (kt + 1 < nK) {
            asm volatile("cp.async.wait_group 1;" ::: "memory");
        } else {
            asm volatile("cp.async.wait_group 0;" ::: "memory");
        }
        __syncthreads();
        if (kt + 2 < nK) LOAD_STAGE((kt + 2) % NSTG, (kt + 2) * BK);

        const uint32_t asb = smb + (uint32_t)(kt % NSTG) * STAGE_BYTES;
        const uint32_t bsb = asb + 128 * PH * 2;

#pragma unroll
        for (int ks = 0; ks < 4; ks++) {
            const int k = ks * 16;
            uint32_t a[4][4], b[4][2];
#pragma unroll
            for (int mt = 0; mt < 4; mt++) {
                const int r = wm * 64 + mt * 16 + a_lr;
                ldm_x4(a[mt], asb + (uint32_t)(r * PH + k + a_kh * 8) * 2);
            }
#pragma unroll
            for (int np = 0; np < 2; np++) {
                const int c = wn * 32 + np * 16 + (b_gr >> 1) * 8 + b_rw;
                uint32_t rr[4];
                ldm_x4(rr, bsb + (uint32_t)(c * PH + k + (b_gr & 1) * 8) * 2);
                b[2 * np][0] = rr[0]; b[2 * np][1] = rr[1];
                b[2 * np + 1][0] = rr[2]; b[2 * np + 1][1] = rr[3];
            }
#pragma unroll
            for (int mt = 0; mt < 4; mt++)
#pragma unroll
                for (int nt = 0; nt < 4; nt++)
                    mma_f16_frag(acc[mt][nt], a[mt], b[nt]);
        }
    }
    __syncthreads();

    // ---- stage accumulator tile to smem ----
    float* tile = sm;                               // [128][TS]
#pragma unroll
    for (int mt = 0; mt < 4; mt++) {
#pragma unroll
        for (int nt = 0; nt < 4; nt++) {
            const int r0 = wm * 64 + mt * 16 + fr;
            const int c0 = wn * 32 + nt * 8 + 2 * fq;
            *(float2*)&tile[r0 * TS + c0]       = make_float2(acc[mt][nt][0], acc[mt][nt][1]);
            *(float2*)&tile[(r0 + 8) * TS + c0] = make_float2(acc[mt][nt][2], acc[mt][nt][3]);
        }
    }
    __syncthreads();

    // ---- concurrent passes: threads 0-127 rows, 128-255 mirror cols ----
    if (tid < 128) {
        const int r = tid;
        const int gr = by * 128 + r;
        const int cs = g_cs[gr], ce = g_ce[gr];
        const int cbase = bx * 128;
        St st; st.init();
        const float* rowp = &tile[r * TS];
#pragma unroll 4
        for (int j4 = 0; j4 < 32; j4++) {
            float4 v = *(const float4*)(rowp + j4 * 4);
            const int jg = cbase + j4 * 4;
            st.upd(v.x, jg + 0, cs, ce);
            st.upd(v.y, jg + 1, cs, ce);
            st.upd(v.z, jg + 2, cs, ce);
            st.upd(v.w, jg + 3, cs, ce);
        }
        st.storeL(&g_part[(size_t)(gr * 32 + bx) * 8]);
    } else if (bx != by) {
        const int c = tid - 128;
        const int gc = bx * 128 + c;
        const int cs = g_cs[gc], ce = g_ce[gc];
        const int rbase = by * 128;
        St st; st.init();
#pragma unroll 4
        for (int r = 0; r < 128; r++)
            st.upd(tile[r * TS + c], rbase + r, cs, ce);
        st.storeL(&g_part[(size_t)(gc * 32 + by) * 8]);
    }

    // ---- ticket cascade ----
    __threadfence();                // make this thread's partial stores visible
    __syncthreads();                // all threads' stores done & fenced
    __shared__ int tkRow, tkCol;
    if (tid == 0) {
        tkRow = atomicAdd(&g_cnt128[by], 1);
        tkCol = (bx != by) ? atomicAdd(&g_cnt128[bx], 1) : -1;
    }
    __syncthreads();
    if (tkRow == NBLK - 1) { finish_block(by, sm, out, B); __syncthreads(); }
    if (tkCol == NBLK - 1) { finish_block(bx, sm, out, B); }
}

// ------------------------------- launch ------------------------------------
extern "C" void kernel_launch(void* const* d_in, const int* in_sizes, int n_in,
                              void* d_out, int out_size) {
    const float* emb = (const float*)d_in[0];
    const void*  lab = d_in[1];
    const int B = in_sizes[1];
    const int D = in_sizes[0] / B;

    cudaFuncSetAttribute(gemm_fused, cudaFuncAttributeMaxDynamicSharedMemorySize, SMEM_GEMM);
    cudaFuncSetAttribute(sort_labels, cudaFuncAttributeMaxDynamicSharedMemorySize, SORT_SMEM);

    sort_labels<<<1, 256, SORT_SMEM>>>(lab, B);
    to_fp16p<<<B, 128>>>(emb, D);

    const int nb = B / 128;
    const int nT = nb * (nb + 1) / 2;           // 528 triangular blocks
    gemm_fused<<<nT, 256, SMEM_GEMM>>>((float*)d_out, B, D);
}

// round 11
// speedup vs baseline: 1.1236x; 1.1236x over previous
#include <cuda_runtime.h>
#include <cuda.h>
#include <cuda_bf16.h>
#include <cuda_fp16.h>
#include <math.h>
#include <stdint.h>

// ---------------------------------------------------------------------------
// CircleLoss, fast-sort edition (R8 structure + parallel counting sort):
//   1) sort_labels : parallel dtype detect + warp-scan stable counting sort
//   2) to_fp16p    : gather-permuted E -> fp16 scratch
//   3) gemm_fused  : triangular grid (528 CTAs), fp16 mma.sync GEMM, 3-stage
//                    cp.async, ldmatrix feeds, row+mirror-col partials (L-form)
//   4) combine     : warp/row merge of 32 partials; last block reduces -> out
// ---------------------------------------------------------------------------

#define MAXB 4096
#define MAXD 512

__device__ __half g_eth[MAXB * MAXD];          // 4 MB permuted fp16 embeddings
__device__ float  g_part[MAXB * 32 * 8];       // 4.2 MB partial states (L-form)
__device__ float4 g_bsum[MAXB / 8];            // per-combine-block sums
__device__ int    g_perm[MAXB];
__device__ int    g_cs[MAXB];
__device__ int    g_ce[MAXB];
__device__ int    g_cnt = 0;                   // combine completion ticket

#define SCALE_C   32.0f
#define MARGIN_P  0.75f
#define MARGIN_N  0.25f
#define OPT_P     1.25f
#define OPT_N     (-0.25f)
#define THETA_C   0.25f
#define NEG_INF   (-INFINITY)

// ------------------------------ helpers ------------------------------------
__device__ __forceinline__ uint32_t smem_u32(const void* p) {
    uint32_t a;
    asm("{ .reg .u64 t; cvta.to.shared.u64 t, %1; cvt.u32.u64 %0, t; }"
        : "=r"(a) : "l"(p));
    return a;
}
__device__ __forceinline__ void cp_async16(uint32_t dst, const void* src) {
    asm volatile("cp.async.cg.shared.global [%0], [%1], 16;" :: "r"(dst), "l"(src));
}
__device__ __forceinline__ void ldm_x4(uint32_t* r, uint32_t addr) {
    asm volatile("ldmatrix.sync.aligned.m8n8.x4.shared.b16 {%0,%1,%2,%3}, [%4];"
        : "=r"(r[0]), "=r"(r[1]), "=r"(r[2]), "=r"(r[3]) : "r"(addr));
}
__device__ __forceinline__ void mma_f16_frag(float* d, const uint32_t* a, const uint32_t* b) {
    asm volatile(
        "mma.sync.aligned.m16n8k16.row.col.f32.f16.f16.f32 "
        "{%0,%1,%2,%3}, {%4,%5,%6,%7}, {%8,%9}, {%0,%1,%2,%3};"
        : "+f"(d[0]), "+f"(d[1]), "+f"(d[2]), "+f"(d[3])
        : "r"(a[0]), "r"(a[1]), "r"(a[2]), "r"(a[3]), "r"(b[0]), "r"(b[1]));
}
__device__ __forceinline__ void lse_add(float& m, float& s, float v) {
    if (v > m) { s = s * expf(m - v) + 1.0f; m = v; }
    else       { s += expf(v - m); }
}
__device__ __forceinline__ void lse_merge(float& m1, float& s1, float m2, float s2) {
    if (m2 == NEG_INF) return;
    if (m2 > m1) { s1 = s1 * expf(m1 - m2) + s2; m1 = m2; }
    else         { s1 += s2 * expf(m2 - m1); }
}
__device__ __forceinline__ float lse_close(float m, float s) {
    return (m == NEG_INF) ? NEG_INF : m + logf(s);
}

struct St {
    float pmin, nmax, m1, s1, m2, s2, m3, s3, m4, s4;
    __device__ __forceinline__ void init() {
        pmin = INFINITY; nmax = NEG_INF;
        m1 = m2 = m3 = m4 = NEG_INF; s1 = s2 = s3 = s4 = 0.f;
    }
    __device__ __forceinline__ void upd(float s, int j, int cs, int ce) {
        if (j >= cs && j < ce) {                       // positive (incl. self)
            pmin = fminf(pmin, s);
            if (s < MARGIN_P) {
                float ip = -SCALE_C * fmaxf(OPT_P - s, 0.0f) * (s - MARGIN_P);
                lse_add(m2, s2, ip);
                if (s + THETA_C < MARGIN_P) lse_add(m1, s1, ip);
            }
        } else {
            nmax = fmaxf(nmax, s);
            if (s > MARGIN_N) {
                float in_ = SCALE_C * fmaxf(s - OPT_N, 0.0f) * (s - MARGIN_N);
                lse_add(m4, s4, in_);
                if (s - THETA_C > MARGIN_N) lse_add(m3, s3, in_);
            }
        }
    }
    __device__ __forceinline__ void mergeShfl(int xorMask) {
        const unsigned FM = 0xffffffffu;
        pmin = fminf(pmin, __shfl_xor_sync(FM, pmin, xorMask));
        nmax = fmaxf(nmax, __shfl_xor_sync(FM, nmax, xorMask));
        float mm, ss;
        mm = __shfl_xor_sync(FM, m1, xorMask); ss = __shfl_xor_sync(FM, s1, xorMask);
        lse_merge(m1, s1, mm, ss);
        mm = __shfl_xor_sync(FM, m2, xorMask); ss = __shfl_xor_sync(FM, s2, xorMask);
        lse_merge(m2, s2, mm, ss);
        mm = __shfl_xor_sync(FM, m3, xorMask); ss = __shfl_xor_sync(FM, s3, xorMask);
        lse_merge(m3, s3, mm, ss);
        mm = __shfl_xor_sync(FM, m4, xorMask); ss = __shfl_xor_sync(FM, s4, xorMask);
        lse_merge(m4, s4, mm, ss);
    }
    // L-form store: 8 floats = pmin, nmax, L1..L4, pad, pad
    __device__ __forceinline__ void storeL(float* p) const {
        ((float4*)p)[0] = make_float4(pmin, nmax, lse_close(m1, s1), lse_close(m2, s2));
        ((float4*)p)[1] = make_float4(lse_close(m3, s3), lse_close(m4, s4), 0.f, 0.f);
    }
};

// ---------------------- parallel deterministic sort -------------------------
// Stable counting sort, 256 threads, chunk = B/256 contiguous labels/thread.
// hist layout [class][chunk] (128 x 256 ushort). Per-class chunk prefix via
// warp shfl-scans; class bases via one warp-scan over class totals.
#define NC 128
#define NCH 256
#define OFF_HIST  (MAXB * 4)                    // 16384
#define OFF_CTOT  (OFF_HIST + NC * NCH * 2)     // 81920
#define OFF_CST   (OFF_CTOT + NC * 4)           // 82432
#define SORT_SMEM (OFF_CST + (NC + 1) * 4 + 64) // 83012 -> fits opt-in smem

__global__ void sort_labels(const void* __restrict__ lab, int B) {
    extern __shared__ char sms[];
    int* slab = (int*)sms;
    unsigned short* hist = (unsigned short*)(sms + OFF_HIST);
    int* ctot   = (int*)(sms + OFF_CTOT);
    int* cstart = (int*)(sms + OFF_CST);

    const int t = threadIdx.x;
    const int lane = t & 31, w = t >> 5;
    const int chk = B / NCH;                    // 16
    const unsigned FM = 0xffffffffu;

    // dtype detect: up to 64 threads vote on int64-view plausibility
    __shared__ int is64;
    {
        const int nProbe = (B < 64) ? B : 64;
        int ok = 1;
        if (t < nProbe) {
            long long v = ((const long long*)lab)[t];
            ok = (v >= 0 && v < (long long)B);
        }
        unsigned m0 = __ballot_sync(FM, ok);    // warps 0,1 cover t<64
        __shared__ unsigned mball[2];
        if (w < 2 && lane == 0) mball[w] = m0;
        __syncthreads();
        if (t == 0) is64 = (mball[0] == FM) && (mball[1] == FM);
        __syncthreads();
    }
    if (is64) {
        const long long* p = (const long long*)lab;
        for (int i = t; i < B; i += NCH) slab[i] = (int)p[i];
    } else {
        const int* p = (const int*)lab;
        for (int i = t; i < B; i += NCH) slab[i] = p[i];
    }
    for (int i = t; i < NC * NCH / 2; i += NCH) ((uint32_t*)hist)[i] = 0;
    __syncthreads();

    // histogram: thread t = chunk t
    for (int k = 0; k < chk; k++) hist[slab[t * chk + k] * NCH + t]++;
    __syncthreads();

    // per-class exclusive chunk-prefix: 8 warps x 16 classes, uint4 packed
    for (int ci = 0; ci < NC / 8; ci++) {
        const int c = w + 8 * ci;
        uint32_t* hp = (uint32_t*)&hist[c * NCH + lane * 8];   // 4 words = 8 ushorts
        uint4 q = *(uint4*)hp;
        unsigned v[8] = { q.x & 0xffffu, q.x >> 16, q.y & 0xffffu, q.y >> 16,
                          q.z & 0xffffu, q.z >> 16, q.w & 0xffffu, q.w >> 16 };
        unsigned e[8]; unsigned s = 0;
#pragma unroll
        for (int j = 0; j < 8; j++) { e[j] = s; s += v[j]; }
        unsigned run = s;
#pragma unroll
        for (int off = 1; off < 32; off <<= 1) {
            unsigned n = __shfl_up_sync(FM, run, off);
            if (lane >= off) run += n;
        }
        const unsigned laneExc = run - s;
#pragma unroll
        for (int j = 0; j < 8; j++) e[j] += laneExc;
        *(uint4*)hp = make_uint4(e[0] | (e[1] << 16), e[2] | (e[3] << 16),
                                 e[4] | (e[5] << 16), e[6] | (e[7] << 16));
        if (lane == 31) ctot[c] = (int)run;     // class total (inclusive)
    }
    __syncthreads();

    // class bases: warp 0 scans 128 totals (4 per lane)
    if (w == 0) {
        int v0 = ctot[lane * 4 + 0], v1 = ctot[lane * 4 + 1];
        int v2 = ctot[lane * 4 + 2], v3 = ctot[lane * 4 + 3];
        int s = v0 + v1 + v2 + v3;
        int run = s;
#pragma unroll
        for (int off = 1; off < 32; off <<= 1) {
            int n = __shfl_up_sync(FM, run, off);
            if (lane >= off) run += n;
        }
        int e = run - s;
        cstart[lane * 4 + 0] = e;
        cstart[lane * 4 + 1] = e + v0;
        cstart[lane * 4 + 2] = e + v0 + v1;
        cstart[lane * 4 + 3] = e + v0 + v1 + v2;
        if (lane == 31) cstart[NC] = run;
    }
    __syncthreads();

    // stable scatter: hist now holds per-class exclusive chunk prefix
    for (int k = 0; k < chk; k++) {
        int i = t * chk + k;
        int c = slab[i];
        int p = hist[c * NCH + t]++;
        g_perm[cstart[c] + p] = i;
    }
    __syncthreads();

    // per-sorted-row class ranges
    for (int r = t; r < B; r += NCH) {
        int c = slab[g_perm[r]];
        g_cs[r] = cstart[c];
        g_ce[r] = cstart[c + 1];
    }
}

// ------------------- permuted fp16 conversion (gather) ----------------------
__global__ __launch_bounds__(128) void to_fp16p(const float* __restrict__ e, int D) {
    const int r = blockIdx.x;
    const int pr = g_perm[r];
    const float4* src = (const float4*)(e + (size_t)pr * D);
    __half2* dst = (__half2*)(g_eth + (size_t)r * D);
    for (int d = threadIdx.x; d < D / 4; d += 128) {
        float4 v = src[d];
        dst[2 * d + 0] = __floats2half2_rn(v.x, v.y);
        dst[2 * d + 1] = __floats2half2_rn(v.z, v.w);
    }
}

// ------------------------ fused GEMM + reduction ----------------------------
#define BK 64
#define PH 72                                  // smem pitch in halves (144 B)
#define STAGE_BYTES (2 * 128 * PH * 2)         // A + B per stage = 36864
#define NSTG 3
#define TS 132                                 // reduction tile pitch (floats)
#define SMEM_GEMM (NSTG * STAGE_BYTES)         // 110592 >= 128*TS*4 = 67584

__global__ __launch_bounds__(256, 2) void gemm_fused(int B, int D) {
    // linear -> triangular (by <= bx)
    const int t = blockIdx.x;
    int bx = (int)((sqrtf(8.0f * t + 1.0f) - 1.0f) * 0.5f);
    while ((bx + 1) * (bx + 2) / 2 <= t) bx++;
    while (bx * (bx + 1) / 2 > t) bx--;
    const int by = t - bx * (bx + 1) / 2;

    extern __shared__ float sm[];
    const uint32_t smb = smem_u32(sm);
    const int tid  = threadIdx.x;
    const int warp = tid >> 5, lane = tid & 31;
    const int wm = warp & 1, wn = warp >> 1;       // 2 x 4 warp grid
    const int fr = lane >> 2, fq = lane & 3;

    const __half* gA = g_eth + (size_t)(by * 128) * D;
    const __half* gB = g_eth + (size_t)(bx * 128) * D;

    float acc[4][4][4];
#pragma unroll
    for (int mt = 0; mt < 4; mt++)
#pragma unroll
        for (int nt = 0; nt < 4; nt++)
#pragma unroll
            for (int e = 0; e < 4; e++) acc[mt][nt][e] = 0.0f;

    const int nK = D / BK;                          // 8

#define LOAD_STAGE(s, k0)                                                      \
    do {                                                                       \
        uint32_t ab = smb + (uint32_t)(s) * STAGE_BYTES;                       \
        uint32_t bb = ab + 128 * PH * 2;                                       \
        _Pragma("unroll")                                                      \
        for (int i = 0; i < 4; i++) {                                          \
            int c = tid + 256 * i;                                             \
            int r = c >> 3;                                                    \
            int kc = (c & 7) << 3;                                             \
            cp_async16(ab + (uint32_t)(r * PH + kc) * 2,                       \
                       gA + (size_t)r * D + (k0) + kc);                        \
            cp_async16(bb + (uint32_t)(r * PH + kc) * 2,                       \
                       gB + (size_t)r * D + (k0) + kc);                        \
        }                                                                      \
        asm volatile("cp.async.commit_group;" ::: "memory");                   \
    } while (0)

    LOAD_STAGE(0, 0);
    LOAD_STAGE(1, BK);

    const int a_lr = lane & 15, a_kh = lane >> 4;     // A: row 0-15, k-half
    const int b_gr = lane >> 3, b_rw = lane & 7;      // B: group 0-3, row 0-7

    for (int kt = 0; kt < nK; kt++) {
        if (kt + 1 < nK) {
            asm volatile("cp.async.wait_group 1;" ::: "memory");
        } else {
            asm volatile("cp.async.wait_group 0;" ::: "memory");
        }
        __syncthreads();
        if (kt + 2 < nK) LOAD_STAGE((kt + 2) % NSTG, (kt + 2) * BK);

        const uint32_t asb = smb + (uint32_t)(kt % NSTG) * STAGE_BYTES;
        const uint32_t bsb = asb + 128 * PH * 2;

#pragma unroll
        for (int ks = 0; ks < 4; ks++) {
            const int k = ks * 16;
            uint32_t a[4][4], b[4][2];
#pragma unroll
            for (int mt = 0; mt < 4; mt++) {
                const int r = wm * 64 + mt * 16 + a_lr;
                ldm_x4(a[mt], asb + (uint32_t)(r * PH + k + a_kh * 8) * 2);
            }
#pragma unroll
            for (int np = 0; np < 2; np++) {
                const int c = wn * 32 + np * 16 + (b_gr >> 1) * 8 + b_rw;
                uint32_t rr[4];
                ldm_x4(rr, bsb + (uint32_t)(c * PH + k + (b_gr & 1) * 8) * 2);
                b[2 * np][0] = rr[0]; b[2 * np][1] = rr[1];
                b[2 * np + 1][0] = rr[2]; b[2 * np + 1][1] = rr[3];
            }
#pragma unroll
            for (int mt = 0; mt < 4; mt++)
#pragma unroll
                for (int nt = 0; nt < 4; nt++)
                    mma_f16_frag(acc[mt][nt], a[mt], b[nt]);
        }
    }
    __syncthreads();

    // ---- stage accumulator tile to smem ----
    float* tile = sm;                               // [128][TS]
#pragma unroll
    for (int mt = 0; mt < 4; mt++) {
#pragma unroll
        for (int nt = 0; nt < 4; nt++) {
            const int r0 = wm * 64 + mt * 16 + fr;
            const int c0 = wn * 32 + nt * 8 + 2 * fq;
            *(float2*)&tile[r0 * TS + c0]       = make_float2(acc[mt][nt][0], acc[mt][nt][1]);
            *(float2*)&tile[(r0 + 8) * TS + c0] = make_float2(acc[mt][nt][2], acc[mt][nt][3]);
        }
    }
    __syncthreads();

    // ---- concurrent passes: threads 0-127 rows, 128-255 mirror cols ----
    if (tid < 128) {
        const int r = tid;
        const int gr = by * 128 + r;
        const int cs = g_cs[gr], ce = g_ce[gr];
        const int cbase = bx * 128;
        St st; st.init();
        const float* rowp = &tile[r * TS];
#pragma unroll 4
        for (int j4 = 0; j4 < 32; j4++) {
            float4 v = *(const float4*)(rowp + j4 * 4);
            const int jg = cbase + j4 * 4;
            st.upd(v.x, jg + 0, cs, ce);
            st.upd(v.y, jg + 1, cs, ce);
            st.upd(v.z, jg + 2, cs, ce);
            st.upd(v.w, jg + 3, cs, ce);
        }
        st.storeL(&g_part[(size_t)(gr * 32 + bx) * 8]);
    } else if (bx != by) {
        const int c = tid - 128;
        const int gc = bx * 128 + c;
        const int cs = g_cs[gc], ce = g_ce[gc];
        const int rbase = by * 128;
        St st; st.init();
#pragma unroll 4
        for (int r = 0; r < 128; r++)
            st.upd(tile[r * TS + c], rbase + r, cs, ce);
        st.storeL(&g_part[(size_t)(gc * 32 + by) * 8]);
    }
}

// ------------------------------- combine ------------------------------------
// One warp per row merges 32 L-form partials; block sums 8 rows; the LAST
// block (atomic ticket) tree-reduces all block sums and writes out[0..3].
__global__ __launch_bounds__(256) void combine(float* __restrict__ out, int B) {
    const int lane = threadIdx.x & 31;
    const int w = threadIdx.x >> 5;
    const int row = blockIdx.x * 8 + w;
    const float* p = &g_part[(size_t)(row * 32 + lane) * 8];
    float4 x0 = ((const float4*)p)[0];
    float4 x1 = ((const float4*)p)[1];
    St st;
    st.pmin = x0.x; st.nmax = x0.y;
    st.m1 = x0.z; st.s1 = 1.f;       // L-form: (m=L, s=1); empty -> L=-inf
    st.m2 = x0.w; st.s2 = 1.f;
    st.m3 = x1.x; st.s3 = 1.f;
    st.m4 = x1.y; st.s4 = 1.f;

    st.mergeShfl(16); st.mergeShfl(8); st.mergeShfl(4); st.mergeShfl(2); st.mergeShfl(1);

    __shared__ float4 sh[8];
    if (lane == 0) {
        float se_pos;
        if (st.m1 > NEG_INF)      se_pos = st.m1 + logf(st.s1);
        else if (st.m2 > NEG_INF) se_pos = st.m2 + logf(st.s2);
        else se_pos = -SCALE_C * fmaxf(OPT_P - st.pmin, 0.0f) * (st.pmin - MARGIN_P);
        float se_neg;
        if (st.m3 > NEG_INF)      se_neg = st.m3 + logf(st.s3);
        else if (st.m4 > NEG_INF) se_neg = st.m4 + logf(st.s4);
        else if (st.nmax > NEG_INF)
            se_neg = SCALE_C * fmaxf(st.nmax - OPT_N, 0.0f) * (st.nmax - MARGIN_N);
        else se_neg = 0.0f;

        float z = se_pos + se_neg;
        float pl = (z > 0.0f) ? (z + log1pf(expf(-z))) : log1pf(expf(z));
        float lowf  = (st.pmin > st.nmax) ? 1.0f : 0.0f;
        float medf  = (lowf != 0.0f && st.pmin > MARGIN_P) ? 1.0f : 0.0f;
        float highf = (medf != 0.0f && st.nmax < MARGIN_N) ? 1.0f : 0.0f;
        sh[w] = make_float4(pl, lowf, medf, highf);
    }
    __syncthreads();

    __shared__ int sticket;
    if (threadIdx.x == 0) {
        float4 a = sh[0];
#pragma unroll
        for (int i = 1; i < 8; i++) {
            float4 b = sh[i];
            a.x += b.x; a.y += b.y; a.z += b.z; a.w += b.w;
        }
        g_bsum[blockIdx.x] = a;
        __threadfence();
        sticket = atomicAdd(&g_cnt, 1);
    }
    __syncthreads();

    const int nb = B / 8;                      // 512 blocks
    if (sticket == nb - 1) {                   // last block finishes the job
        __shared__ float4 sh4[256];
        const int tid = threadIdx.x;
        float4 a = __ldcg(&g_bsum[tid]);
        float4 b = __ldcg(&g_bsum[tid + 256]);
        sh4[tid] = make_float4(a.x + b.x, a.y + b.y, a.z + b.z, a.w + b.w);
        __syncthreads();
        for (int off = 128; off > 0; off >>= 1) {
            if (tid < off) {
                float4 x = sh4[tid], y = sh4[tid + off];
                sh4[tid] = make_float4(x.x + y.x, x.y + y.y, x.z + y.z, x.w + y.w);
            }
            __syncthreads();
        }
        if (tid == 0) {
            float inv = 1.0f / (float)B;
            out[0] = sh4[0].x * inv;
            out[1] = sh4[0].y * inv;
            out[2] = sh4[0].z * inv;
            out[3] = sh4[0].w * inv;
            g_cnt = 0;                         // reset for next graph replay
        }
    }
}

// ------------------------------- launch ------------------------------------
extern "C" void kernel_launch(void* const* d_in, const int* in_sizes, int n_in,
                              void* d_out, int out_size) {
    const float* emb = (const float*)d_in[0];
    const void*  lab = d_in[1];
    const int B = in_sizes[1];
    const int D = in_sizes[0] / B;

    cudaFuncSetAttribute(gemm_fused, cudaFuncAttributeMaxDynamicSharedMemorySize, SMEM_GEMM);
    cudaFuncSetAttribute(sort_labels, cudaFuncAttributeMaxDynamicSharedMemorySize, SORT_SMEM);

    sort_labels<<<1, 256, SORT_SMEM>>>(lab, B);
    to_fp16p<<<B, 128>>>(emb, D);

    const int nb = B / 128;
    const int nT = nb * (nb + 1) / 2;           // 528 triangular blocks
    gemm_fused<<<nT, 256, SMEM_GEMM>>>(B, D);

    combine<<<B / 8, 256>>>((float*)d_out, B);
}

// round 12
// speedup vs baseline: 1.3169x; 1.1721x over previous
#include <cuda_runtime.h>
#include <cuda.h>
#include <cuda_bf16.h>
#include <cuda_fp16.h>
#include <math.h>
#include <stdint.h>

// ---------------------------------------------------------------------------
// CircleLoss, 32-warp/SM edition:
//   1) sort_labels : parallel dtype detect + warp-scan stable counting sort
//   2) to_fp16p    : gather-permuted E -> fp16 scratch
//   3) gemm_fused  : triangular grid (528 CTAs), 512 threads (16 warps of
//                    32x32), BK=64, 3-stage cp.async, ldmatrix feeds,
//                    row+mirror-col partials (L-form), 2 CTAs/SM = 32 warps.
//   4) combine     : branch-free warp LSE (max-butterfly + exp + sum-butterfly)
//                    + last-block final reduce -> out[0..3]
// ---------------------------------------------------------------------------

#define MAXB 4096
#define MAXD 512

__device__ __half g_eth[MAXB * MAXD];          // 4 MB permuted fp16 embeddings
__device__ float  g_part[MAXB * 32 * 8];       // 4.2 MB partial states (L-form)
__device__ float4 g_bsum[MAXB / 8];            // per-combine-block sums
__device__ int    g_perm[MAXB];
__device__ int    g_cs[MAXB];
__device__ int    g_ce[MAXB];
__device__ int    g_cnt = 0;                   // combine completion ticket

#define SCALE_C   32.0f
#define MARGIN_P  0.75f
#define MARGIN_N  0.25f
#define OPT_P     1.25f
#define OPT_N     (-0.25f)
#define THETA_C   0.25f
#define NEG_INF   (-INFINITY)

// ------------------------------ helpers ------------------------------------
__device__ __forceinline__ uint32_t smem_u32(const void* p) {
    uint32_t a;
    asm("{ .reg .u64 t; cvta.to.shared.u64 t, %1; cvt.u32.u64 %0, t; }"
        : "=r"(a) : "l"(p));
    return a;
}
__device__ __forceinline__ void cp_async16(uint32_t dst, const void* src) {
    asm volatile("cp.async.cg.shared.global [%0], [%1], 16;" :: "r"(dst), "l"(src));
}
__device__ __forceinline__ void ldm_x4(uint32_t* r, uint32_t addr) {
    asm volatile("ldmatrix.sync.aligned.m8n8.x4.shared.b16 {%0,%1,%2,%3}, [%4];"
        : "=r"(r[0]), "=r"(r[1]), "=r"(r[2]), "=r"(r[3]) : "r"(addr));
}
__device__ __forceinline__ void mma_f16_frag(float* d, const uint32_t* a, const uint32_t* b) {
    asm volatile(
        "mma.sync.aligned.m16n8k16.row.col.f32.f16.f16.f32 "
        "{%0,%1,%2,%3}, {%4,%5,%6,%7}, {%8,%9}, {%0,%1,%2,%3};"
        : "+f"(d[0]), "+f"(d[1]), "+f"(d[2]), "+f"(d[3])
        : "r"(a[0]), "r"(a[1]), "r"(a[2]), "r"(a[3]), "r"(b[0]), "r"(b[1]));
}
__device__ __forceinline__ void lse_add(float& m, float& s, float v) {
    if (v > m) { s = s * expf(m - v) + 1.0f; m = v; }
    else       { s += expf(v - m); }
}
__device__ __forceinline__ void lse_merge(float& m1, float& s1, float m2, float s2) {
    if (m2 == NEG_INF) return;
    if (m2 > m1) { s1 = s1 * expf(m1 - m2) + s2; m1 = m2; }
    else         { s1 += s2 * expf(m2 - m1); }
}
__device__ __forceinline__ float lse_close(float m, float s) {
    return (m == NEG_INF) ? NEG_INF : m + logf(s);
}

struct St {
    float pmin, nmax, m1, s1, m2, s2, m3, s3, m4, s4;
    __device__ __forceinline__ void init() {
        pmin = INFINITY; nmax = NEG_INF;
        m1 = m2 = m3 = m4 = NEG_INF; s1 = s2 = s3 = s4 = 0.f;
    }
    __device__ __forceinline__ void upd(float s, int j, int cs, int ce) {
        if (j >= cs && j < ce) {                       // positive (incl. self)
            pmin = fminf(pmin, s);
            if (s < MARGIN_P) {
                float ip = -SCALE_C * fmaxf(OPT_P - s, 0.0f) * (s - MARGIN_P);
                lse_add(m2, s2, ip);
                if (s + THETA_C < MARGIN_P) lse_add(m1, s1, ip);
            }
        } else {
            nmax = fmaxf(nmax, s);
            if (s > MARGIN_N) {
                float in_ = SCALE_C * fmaxf(s - OPT_N, 0.0f) * (s - MARGIN_N);
                lse_add(m4, s4, in_);
                if (s - THETA_C > MARGIN_N) lse_add(m3, s3, in_);
            }
        }
    }
    __device__ __forceinline__ void mergeShfl(int xorMask) {
        const unsigned FM = 0xffffffffu;
        pmin = fminf(pmin, __shfl_xor_sync(FM, pmin, xorMask));
        nmax = fmaxf(nmax, __shfl_xor_sync(FM, nmax, xorMask));
        float mm, ss;
        mm = __shfl_xor_sync(FM, m1, xorMask); ss = __shfl_xor_sync(FM, s1, xorMask);
        lse_merge(m1, s1, mm, ss);
        mm = __shfl_xor_sync(FM, m2, xorMask); ss = __shfl_xor_sync(FM, s2, xorMask);
        lse_merge(m2, s2, mm, ss);
        mm = __shfl_xor_sync(FM, m3, xorMask); ss = __shfl_xor_sync(FM, s3, xorMask);
        lse_merge(m3, s3, mm, ss);
        mm = __shfl_xor_sync(FM, m4, xorMask); ss = __shfl_xor_sync(FM, s4, xorMask);
        lse_merge(m4, s4, mm, ss);
    }
    // L-form store: 8 floats = pmin, nmax, L1..L4, pad, pad
    __device__ __forceinline__ void storeL(float* p) const {
        ((float4*)p)[0] = make_float4(pmin, nmax, lse_close(m1, s1), lse_close(m2, s2));
        ((float4*)p)[1] = make_float4(lse_close(m3, s3), lse_close(m4, s4), 0.f, 0.f);
    }
};

// ---------------------- parallel deterministic sort -------------------------
#define NC 128
#define NCH 256
#define OFF_HIST  (MAXB * 4)
#define OFF_CTOT  (OFF_HIST + NC * NCH * 2)
#define OFF_CST   (OFF_CTOT + NC * 4)
#define SORT_SMEM (OFF_CST + (NC + 1) * 4 + 64)

__global__ void sort_labels(const void* __restrict__ lab, int B) {
    extern __shared__ char sms[];
    int* slab = (int*)sms;
    unsigned short* hist = (unsigned short*)(sms + OFF_HIST);
    int* ctot   = (int*)(sms + OFF_CTOT);
    int* cstart = (int*)(sms + OFF_CST);

    const int t = threadIdx.x;
    const int lane = t & 31, w = t >> 5;
    const int chk = B / NCH;
    const unsigned FM = 0xffffffffu;

    __shared__ int is64;
    {
        const int nProbe = (B < 64) ? B : 64;
        int ok = 1;
        if (t < nProbe) {
            long long v = ((const long long*)lab)[t];
            ok = (v >= 0 && v < (long long)B);
        }
        unsigned m0 = __ballot_sync(FM, ok);
        __shared__ unsigned mball[2];
        if (w < 2 && lane == 0) mball[w] = m0;
        __syncthreads();
        if (t == 0) is64 = (mball[0] == FM) && (mball[1] == FM);
        __syncthreads();
    }
    if (is64) {
        const long long* p = (const long long*)lab;
        for (int i = t; i < B; i += NCH) slab[i] = (int)p[i];
    } else {
        const int* p = (const int*)lab;
        for (int i = t; i < B; i += NCH) slab[i] = p[i];
    }
    for (int i = t; i < NC * NCH / 2; i += NCH) ((uint32_t*)hist)[i] = 0;
    __syncthreads();

    for (int k = 0; k < chk; k++) hist[slab[t * chk + k] * NCH + t]++;
    __syncthreads();

    for (int ci = 0; ci < NC / 8; ci++) {
        const int c = w + 8 * ci;
        uint32_t* hp = (uint32_t*)&hist[c * NCH + lane * 8];
        uint4 q = *(uint4*)hp;
        unsigned v[8] = { q.x & 0xffffu, q.x >> 16, q.y & 0xffffu, q.y >> 16,
                          q.z & 0xffffu, q.z >> 16, q.w & 0xffffu, q.w >> 16 };
        unsigned e[8]; unsigned s = 0;
#pragma unroll
        for (int j = 0; j < 8; j++) { e[j] = s; s += v[j]; }
        unsigned run = s;
#pragma unroll
        for (int off = 1; off < 32; off <<= 1) {
            unsigned n = __shfl_up_sync(FM, run, off);
            if (lane >= off) run += n;
        }
        const unsigned laneExc = run - s;
#pragma unroll
        for (int j = 0; j < 8; j++) e[j] += laneExc;
        *(uint4*)hp = make_uint4(e[0] | (e[1] << 16), e[2] | (e[3] << 16),
                                 e[4] | (e[5] << 16), e[6] | (e[7] << 16));
        if (lane == 31) ctot[c] = (int)run;
    }
    __syncthreads();

    if (w == 0) {
        int v0 = ctot[lane * 4 + 0], v1 = ctot[lane * 4 + 1];
        int v2 = ctot[lane * 4 + 2], v3 = ctot[lane * 4 + 3];
        int s = v0 + v1 + v2 + v3;
        int run = s;
#pragma unroll
        for (int off = 1; off < 32; off <<= 1) {
            int n = __shfl_up_sync(FM, run, off);
            if (lane >= off) run += n;
        }
        int e = run - s;
        cstart[lane * 4 + 0] = e;
        cstart[lane * 4 + 1] = e + v0;
        cstart[lane * 4 + 2] = e + v0 + v1;
        cstart[lane * 4 + 3] = e + v0 + v1 + v2;
        if (lane == 31) cstart[NC] = run;
    }
    __syncthreads();

    for (int k = 0; k < chk; k++) {
        int i = t * chk + k;
        int c = slab[i];
        int p = hist[c * NCH + t]++;
        g_perm[cstart[c] + p] = i;
    }
    __syncthreads();

    for (int r = t; r < B; r += NCH) {
        int c = slab[g_perm[r]];
        g_cs[r] = cstart[c];
        g_ce[r] = cstart[c + 1];
    }
}

// ------------------- permuted fp16 conversion (gather) ----------------------
__global__ __launch_bounds__(128) void to_fp16p(const float* __restrict__ e, int D) {
    const int r = blockIdx.x;
    const int pr = g_perm[r];
    const float4* src = (const float4*)(e + (size_t)pr * D);
    __half2* dst = (__half2*)(g_eth + (size_t)r * D);
    for (int d = threadIdx.x; d < D / 4; d += 128) {
        float4 v = src[d];
        dst[2 * d + 0] = __floats2half2_rn(v.x, v.y);
        dst[2 * d + 1] = __floats2half2_rn(v.z, v.w);
    }
}

// ------------------------ fused GEMM + reduction ----------------------------
// Triangular grid. 128x128 CTA tile, 16 warps (4m x 4n) of 32x32, BK=64,
// 3-stage cp.async, ldmatrix feeds. 512 threads, 2 CTAs/SM = 32 warps/SM.
#define BK 64
#define PH 72                                  // smem pitch in halves (144 B)
#define STAGE_BYTES (2 * 128 * PH * 2)         // A + B per stage = 36864
#define NSTG 3
#define TS 132                                 // reduction tile pitch (floats)
#define SMEM_GEMM (NSTG * STAGE_BYTES)         // 110592 >= 128*TS*4 = 67584

__global__ __launch_bounds__(512, 2) void gemm_fused(int B, int D) {
    // linear -> triangular (by <= bx)
    const int t = blockIdx.x;
    int bx = (int)((sqrtf(8.0f * t + 1.0f) - 1.0f) * 0.5f);
    while ((bx + 1) * (bx + 2) / 2 <= t) bx++;
    while (bx * (bx + 1) / 2 > t) bx--;
    const int by = t - bx * (bx + 1) / 2;

    extern __shared__ float sm[];
    const uint32_t smb = smem_u32(sm);
    const int tid  = threadIdx.x;
    const int warp = tid >> 5, lane = tid & 31;
    const int wm = warp & 3, wn = warp >> 2;       // 4 x 4 warp grid
    const int fr = lane >> 2, fq = lane & 3;

    const __half* gA = g_eth + (size_t)(by * 128) * D;
    const __half* gB = g_eth + (size_t)(bx * 128) * D;

    float acc[2][4][4];
#pragma unroll
    for (int mt = 0; mt < 2; mt++)
#pragma unroll
        for (int nt = 0; nt < 4; nt++)
#pragma unroll
            for (int e = 0; e < 4; e++) acc[mt][nt][e] = 0.0f;

    const int nK = D / BK;                          // 8

#define LOAD_STAGE(s, k0)                                                      \
    do {                                                                       \
        uint32_t ab = smb + (uint32_t)(s) * STAGE_BYTES;                       \
        uint32_t bb = ab + 128 * PH * 2;                                       \
        _Pragma("unroll")                                                      \
        for (int i = 0; i < 2; i++) {                                          \
            int c = tid + 512 * i;                                             \
            int r = c >> 3;                                                    \
            int kc = (c & 7) << 3;                                             \
            cp_async16(ab + (uint32_t)(r * PH + kc) * 2,                       \
                       gA + (size_t)r * D + (k0) + kc);                        \
            cp_async16(bb + (uint32_t)(r * PH + kc) * 2,                       \
                       gB + (size_t)r * D + (k0) + kc);                        \
        }                                                                      \
        asm volatile("cp.async.commit_group;" ::: "memory");                   \
    } while (0)

    LOAD_STAGE(0, 0);
    LOAD_STAGE(1, BK);

    const int a_lr = lane & 15, a_kh = lane >> 4;     // A: row 0-15, k-half
    const int b_gr = lane >> 3, b_rw = lane & 7;      // B: group 0-3, row 0-7

    for (int kt = 0; kt < nK; kt++) {
        if (kt + 1 < nK) {
            asm volatile("cp.async.wait_group 1;" ::: "memory");
        } else {
            asm volatile("cp.async.wait_group 0;" ::: "memory");
        }
        __syncthreads();
        if (kt + 2 < nK) LOAD_STAGE((kt + 2) % NSTG, (kt + 2) * BK);

        const uint32_t asb = smb + (uint32_t)(kt % NSTG) * STAGE_BYTES;
        const uint32_t bsb = asb + 128 * PH * 2;

#pragma unroll
        for (int ks = 0; ks < 4; ks++) {
            const int k = ks * 16;
            uint32_t a[2][4], b[4][2];
#pragma unroll
            for (int mt = 0; mt < 2; mt++) {
                const int r = wm * 32 + mt * 16 + a_lr;
                ldm_x4(a[mt], asb + (uint32_t)(r * PH + k + a_kh * 8) * 2);
            }
#pragma unroll
            for (int np = 0; np < 2; np++) {
                const int c = wn * 32 + np * 16 + (b_gr >> 1) * 8 + b_rw;
                uint32_t rr[4];
                ldm_x4(rr, bsb + (uint32_t)(c * PH + k + (b_gr & 1) * 8) * 2);
                b[2 * np][0] = rr[0]; b[2 * np][1] = rr[1];
                b[2 * np + 1][0] = rr[2]; b[2 * np + 1][1] = rr[3];
            }
#pragma unroll
            for (int mt = 0; mt < 2; mt++)
#pragma unroll
                for (int nt = 0; nt < 4; nt++)
                    mma_f16_frag(acc[mt][nt], a[mt], b[nt]);
        }
    }
    __syncthreads();

    // ---- stage accumulator tile to smem ----
    float* tile = sm;                               // [128][TS]
#pragma unroll
    for (int mt = 0; mt < 2; mt++) {
#pragma unroll
        for (int nt = 0; nt < 4; nt++) {
            const int r0 = wm * 32 + mt * 16 + fr;
            const int c0 = wn * 32 + nt * 8 + 2 * fq;
            *(float2*)&tile[r0 * TS + c0]       = make_float2(acc[mt][nt][0], acc[mt][nt][1]);
            *(float2*)&tile[(r0 + 8) * TS + c0] = make_float2(acc[mt][nt][2], acc[mt][nt][3]);
        }
    }
    __syncthreads();

    // ---- concurrent passes, 2 threads per row/col (shfl-paired) ----
    if (tid < 256) {
        const int r = tid >> 1, h = tid & 1;
        const int gr = by * 128 + r;
        const int cs = g_cs[gr], ce = g_ce[gr];
        const int cbase = bx * 128 + h * 64;
        St st; st.init();
        const float* rowp = &tile[r * TS + h * 64];
#pragma unroll 4
        for (int j4 = 0; j4 < 16; j4++) {
            float4 v = *(const float4*)(rowp + j4 * 4);
            const int jg = cbase + j4 * 4;
            st.upd(v.x, jg + 0, cs, ce);
            st.upd(v.y, jg + 1, cs, ce);
            st.upd(v.z, jg + 2, cs, ce);
            st.upd(v.w, jg + 3, cs, ce);
        }
        st.mergeShfl(1);
        if (h == 0) st.storeL(&g_part[(size_t)(gr * 32 + bx) * 8]);
    } else if (bx != by) {
        const int u = tid - 256;
        const int c = u >> 1, h = u & 1;
        const int gc = bx * 128 + c;
        const int cs = g_cs[gc], ce = g_ce[gc];
        const int rbase = by * 128 + h * 64;
        St st; st.init();
#pragma unroll 4
        for (int r = 0; r < 64; r++)
            st.upd(tile[(h * 64 + r) * TS + c], rbase + r, cs, ce);
        st.mergeShfl(1);
        if (h == 0) st.storeL(&g_part[(size_t)(gc * 32 + by) * 8]);
    }
}

// ------------------------------- combine ------------------------------------
// One warp per row: branch-free LSE over 32 L-form partials (max-butterfly,
// exp, sum-butterfly); block sums 8 rows; last block reduces -> out[0..3].
__global__ __launch_bounds__(256) void combine(float* __restrict__ out, int B) {
    const int lane = threadIdx.x & 31;
    const int w = threadIdx.x >> 5;
    const int row = blockIdx.x * 8 + w;
    const float4* p = (const float4*)&g_part[(size_t)(row * 32 + lane) * 8];
    float4 x0 = p[0], x1 = p[1];
    float pmin = x0.x, nmax = x0.y;
    float L1 = x0.z, L2 = x0.w, L3 = x1.x, L4 = x1.y;
    float M1 = L1, M2 = L2, M3 = L3, M4 = L4;
    const unsigned FM = 0xffffffffu;
#pragma unroll
    for (int o = 16; o > 0; o >>= 1) {
        pmin = fminf(pmin, __shfl_xor_sync(FM, pmin, o));
        nmax = fmaxf(nmax, __shfl_xor_sync(FM, nmax, o));
        M1 = fmaxf(M1, __shfl_xor_sync(FM, M1, o));
        M2 = fmaxf(M2, __shfl_xor_sync(FM, M2, o));
        M3 = fmaxf(M3, __shfl_xor_sync(FM, M3, o));
        M4 = fmaxf(M4, __shfl_xor_sync(FM, M4, o));
    }
    // per-lane terms (L=-inf, M finite -> 0; M=-inf cases are never used)
    float e1 = expf(L1 - M1), e2 = expf(L2 - M2);
    float e3 = expf(L3 - M3), e4 = expf(L4 - M4);
#pragma unroll
    for (int o = 16; o > 0; o >>= 1) {
        e1 += __shfl_xor_sync(FM, e1, o);
        e2 += __shfl_xor_sync(FM, e2, o);
        e3 += __shfl_xor_sync(FM, e3, o);
        e4 += __shfl_xor_sync(FM, e4, o);
    }

    __shared__ float4 sh[8];
    if (lane == 0) {
        float se_pos;
        if (M1 > NEG_INF)      se_pos = M1 + logf(e1);
        else if (M2 > NEG_INF) se_pos = M2 + logf(e2);
        else se_pos = -SCALE_C * fmaxf(OPT_P - pmin, 0.0f) * (pmin - MARGIN_P);
        float se_neg;
        if (M3 > NEG_INF)      se_neg = M3 + logf(e3);
        else if (M4 > NEG_INF) se_neg = M4 + logf(e4);
        else if (nmax > NEG_INF)
            se_neg = SCALE_C * fmaxf(nmax - OPT_N, 0.0f) * (nmax - MARGIN_N);
        else se_neg = 0.0f;

        float z = se_pos + se_neg;
        float pl = (z > 0.0f) ? (z + log1pf(expf(-z))) : log1pf(expf(z));
        float lowf  = (pmin > nmax) ? 1.0f : 0.0f;
        float medf  = (lowf != 0.0f && pmin > MARGIN_P) ? 1.0f : 0.0f;
        float highf = (medf != 0.0f && nmax < MARGIN_N) ? 1.0f : 0.0f;
        sh[w] = make_float4(pl, lowf, medf, highf);
    }
    __syncthreads();

    __shared__ int sticket;
    if (threadIdx.x == 0) {
        float4 a = sh[0];
#pragma unroll
        for (int i = 1; i < 8; i++) {
            float4 b = sh[i];
            a.x += b.x; a.y += b.y; a.z += b.z; a.w += b.w;
        }
        g_bsum[blockIdx.x] = a;
        __threadfence();
        sticket = atomicAdd(&g_cnt, 1);
    }
    __syncthreads();

    const int nb = B / 8;                      // 512 blocks
    if (sticket == nb - 1) {                   // last block finishes the job
        __shared__ float4 sh4[256];
        const int tid = threadIdx.x;
        float4 a = __ldcg(&g_bsum[tid]);
        float4 b = __ldcg(&g_bsum[tid + 256]);
        sh4[tid] = make_float4(a.x + b.x, a.y + b.y, a.z + b.z, a.w + b.w);
        __syncthreads();
        for (int off = 128; off > 0; off >>= 1) {
            if (tid < off) {
                float4 x = sh4[tid], y = sh4[tid + off];
                sh4[tid] = make_float4(x.x + y.x, x.y + y.y, x.z + y.z, x.w + y.w);
            }
            __syncthreads();
        }
        if (tid == 0) {
            float inv = 1.0f / (float)B;
            out[0] = sh4[0].x * inv;
            out[1] = sh4[0].y * inv;
            out[2] = sh4[0].z * inv;
            out[3] = sh4[0].w * inv;
            g_cnt = 0;                         // reset for next graph replay
        }
    }
}

// ------------------------------- launch ------------------------------------
extern "C" void kernel_launch(void* const* d_in, const int* in_sizes, int n_in,
                              void* d_out, int out_size) {
    const float* emb = (const float*)d_in[0];
    const void*  lab = d_in[1];
    const int B = in_sizes[1];
    const int D = in_sizes[0] / B;

    cudaFuncSetAttribute(gemm_fused, cudaFuncAttributeMaxDynamicSharedMemorySize, SMEM_GEMM);
    cudaFuncSetAttribute(sort_labels, cudaFuncAttributeMaxDynamicSharedMemorySize, SORT_SMEM);

    sort_labels<<<1, 256, SORT_SMEM>>>(lab, B);
    to_fp16p<<<B, 128>>>(emb, D);

    const int nb = B / 128;
    const int nT = nb * (nb + 1) / 2;           // 528 triangular blocks
    gemm_fused<<<nT, 512, SMEM_GEMM>>>(B, D);

    combine<<<B / 8, 256>>>((float*)d_out, B);
}